// round 2
// baseline (speedup 1.0000x reference)
#include <cuda_runtime.h>
#include <math.h>

// Problem shape (fixed by the reference): x[N,K], w[M,K], out[N,M]
#define N_ 1024
#define K_ 256
#define M_ 1024

// Scratch (allocs are forbidden; __device__ globals are the sanctioned path)
__device__ float g_bT[K_][M_];        // bT[k][m] = |w[m][k]|   (1 MB, L2-resident)
__device__ float g_bmax_part[256];    // per-block partial maxima of |w|

// ---------------------------------------------------------------------------
// Kernel A: abs + transpose of w, plus per-block max partials.
// grid = (M/32, K/32) = (32, 8); block = (32, 8) = 256 threads.
// ---------------------------------------------------------------------------
__global__ void absT_kernel(const float* __restrict__ w) {
    __shared__ float tile[32][33];     // +1 pad: conflict-free transposed reads
    __shared__ float red[256];

    const int bm = blockIdx.x * 32;    // m-tile base
    const int bk = blockIdx.y * 32;    // k-tile base
    const int tx = threadIdx.x;        // 0..31
    const int ty = threadIdx.y;        // 0..7
    const int tid = ty * 32 + tx;

    float lmax = 0.0f;
    #pragma unroll
    for (int i = 0; i < 4; i++) {
        const int m = bm + ty + i * 8;
        const float v = fabsf(w[m * K_ + (bk + tx)]);   // coalesced read
        tile[ty + i * 8][tx] = v;
        lmax = fmaxf(lmax, v);
    }
    __syncthreads();

    #pragma unroll
    for (int i = 0; i < 4; i++) {
        const int k = bk + ty + i * 8;
        g_bT[k][bm + tx] = tile[tx][ty + i * 8];        // coalesced write
    }

    // block max reduction -> one partial per block
    red[tid] = lmax;
    __syncthreads();
    #pragma unroll
    for (int s = 128; s > 0; s >>= 1) {
        if (tid < s) red[tid] = fmaxf(red[tid], red[tid + s]);
        __syncthreads();
    }
    if (tid == 0) g_bmax_part[blockIdx.y * gridDim.x + blockIdx.x] = red[0];
}

// ---------------------------------------------------------------------------
// Kernel B: one block per output row n. Exact candidate pruning:
//   keep k iff  a[n,k] + Bmax >= amax_n   (fp-monotone => exact vs reference)
// then out[n, m] = max over candidates of (a_j + bT[k_j][m]).
// block = 256 threads; thread t owns m = 4t..4t+3 (float4).
// ---------------------------------------------------------------------------
__global__ void tropical_rows_kernel(const float* __restrict__ x,
                                     float* __restrict__ out) {
    __shared__ float red[256];
    __shared__ float sh_a[256];
    __shared__ int   sh_k[256];
    __shared__ int   sh_cnt;

    const int n   = blockIdx.x;
    const int tid = threadIdx.x;

    // ---- global Bmax from the 256 partials ----
    red[tid] = g_bmax_part[tid];
    __syncthreads();
    #pragma unroll
    for (int s = 128; s > 0; s >>= 1) {
        if (tid < s) red[tid] = fmaxf(red[tid], red[tid + s]);
        __syncthreads();
    }
    const float Bmax = red[0];
    __syncthreads();                   // red[] is reused below

    // ---- row of |x| and its max ----
    const float a = fabsf(x[n * K_ + tid]);
    red[tid] = a;
    __syncthreads();
    #pragma unroll
    for (int s = 128; s > 0; s >>= 1) {
        if (tid < s) red[tid] = fmaxf(red[tid], red[tid + s]);
        __syncthreads();
    }
    const float amax = red[0];

    if (tid == 0) sh_cnt = 0;
    __syncthreads();

    // ---- exact pruning + compaction (order irrelevant) ----
    if (a + Bmax >= amax) {            // >= guarantees cnt >= 1 (argmax survives)
        const int p = atomicAdd(&sh_cnt, 1);
        sh_a[p] = a;
        sh_k[p] = tid;
    }
    __syncthreads();
    const int cnt = sh_cnt;

    // ---- sweep candidates over 4 m's per thread ----
    float4 acc = make_float4(-INFINITY, -INFINITY, -INFINITY, -INFINITY);
    #pragma unroll 2
    for (int j = 0; j < cnt; j++) {
        const float aj = sh_a[j];
        const int   kj = sh_k[j];
        const float4 b = reinterpret_cast<const float4*>(&g_bT[kj][0])[tid];
        acc.x = fmaxf(acc.x, aj + b.x);
        acc.y = fmaxf(acc.y, aj + b.y);
        acc.z = fmaxf(acc.z, aj + b.z);
        acc.w = fmaxf(acc.w, aj + b.w);
    }
    reinterpret_cast<float4*>(out + n * M_)[tid] = acc;
}

// ---------------------------------------------------------------------------
extern "C" void kernel_launch(void* const* d_in, const int* in_sizes, int n_in,
                              void* d_out, int out_size) {
    const float* x = (const float*)d_in[0];   // [N, K] fp32
    const float* w = (const float*)d_in[1];   // [M, K] fp32
    float* out     = (float*)d_out;           // [N, M] fp32

    (void)in_sizes; (void)n_in; (void)out_size;

    absT_kernel<<<dim3(M_ / 32, K_ / 32), dim3(32, 8)>>>(w);
    tropical_rows_kernel<<<N_, 256>>>(x, out);
}

// round 3
// speedup vs baseline: 1.1079x; 1.1079x over previous
#include <cuda_runtime.h>
#include <math.h>

// Problem shape (fixed by the reference): x[N,K], w[M,K], out[N,M]
#define N_ 1024
#define K_ 256
#define M_ 1024

// Scratch (allocs forbidden; __device__ globals are the sanctioned path)
__device__ float        g_bT[K_][M_];   // bT[k][m] = |w[m][k]|  (1 MB, L2-resident)
__device__ unsigned int g_bmax_bits;    // bits of max|w|; nonneg fp32 orders as uint.
                                        // Monotone re-convergence on identical inputs
                                        // => graph-replay deterministic.

// ---------------------------------------------------------------------------
// Kernel A: abs + transpose of w, plus Bmax via warp-redux + atomicMax.
// grid = (M/32, K/32) = (32, 8); block = (32, 8) = 256 threads (1 warp per ty).
// ---------------------------------------------------------------------------
__global__ void absT_kernel(const float* __restrict__ w) {
    __shared__ float tile[32][33];       // +1 pad: conflict-free transposed reads

    const int bm = blockIdx.x * 32;      // m-tile base
    const int bk = blockIdx.y * 32;      // k-tile base
    const int tx = threadIdx.x;          // 0..31 (lane)
    const int ty = threadIdx.y;          // 0..7  (warp)

    float lmax = 0.0f;
    #pragma unroll
    for (int i = 0; i < 4; i++) {
        const int m = bm + ty + i * 8;
        const float v = fabsf(w[m * K_ + (bk + tx)]);    // coalesced read
        tile[ty + i * 8][tx] = v;
        lmax = fmaxf(lmax, v);
    }
    __syncthreads();

    #pragma unroll
    for (int i = 0; i < 4; i++) {
        const int k = bk + ty + i * 8;
        g_bT[k][bm + tx] = tile[tx][ty + i * 8];         // coalesced write
    }

    // warp max (single REDUX.SYNC) -> one atomic per warp
    const unsigned int wm = __reduce_max_sync(0xffffffffu, __float_as_uint(lmax));
    if (tx == 0) atomicMax(&g_bmax_bits, wm);
}

// ---------------------------------------------------------------------------
// Kernel B: one block per output row n. Exact candidate pruning:
//   keep k iff  a[n,k] + Bmax >= amax_n   (fp-monotone => exact vs reference)
// then out[n, m] = max over candidates of (a_j + bT[k_j][m]).
// 256 threads; thread t owns m = 4t..4t+3 (float4). Only TWO barriers.
// ---------------------------------------------------------------------------
__global__ void tropical_rows_kernel(const float* __restrict__ x,
                                     float* __restrict__ out) {
    __shared__ float wmax[8];
    __shared__ float sh_a[256];
    __shared__ int   sh_k[256];
    __shared__ int   sh_cnt;

    const int n    = blockIdx.x;
    const int tid  = threadIdx.x;
    const int lane = tid & 31;
    const int wid  = tid >> 5;

    // ---- row of |x|, warp max via REDUX, 8-way cross-warp max ----
    const float a = fabsf(x[n * K_ + tid]);
    const unsigned int wm = __reduce_max_sync(0xffffffffu, __float_as_uint(a));
    if (tid == 0) sh_cnt = 0;
    if (lane == 0) wmax[wid] = __uint_as_float(wm);
    __syncthreads();                                     // barrier #1

    float amax = wmax[0];
    #pragma unroll
    for (int i = 1; i < 8; i++) amax = fmaxf(amax, wmax[i]);

    const float Bmax = __uint_as_float(g_bmax_bits);     // uniform LDG

    // ---- exact pruning + ballot compaction (one atomic per warp) ----
    const bool keep = (a + Bmax >= amax);                // >= keeps argmax => cnt >= 1
    const unsigned int bal = __ballot_sync(0xffffffffu, keep);
    int base = 0;
    if (lane == 0) base = atomicAdd(&sh_cnt, __popc(bal));
    base = __shfl_sync(0xffffffffu, base, 0);
    if (keep) {
        const int p = base + __popc(bal & ((1u << lane) - 1u));
        sh_a[p] = a;
        sh_k[p] = tid;
    }
    __syncthreads();                                     // barrier #2
    const int cnt = sh_cnt;

    // ---- sweep candidates over 4 m's per thread (coalesced float4) ----
    float4 acc = make_float4(-INFINITY, -INFINITY, -INFINITY, -INFINITY);
    #pragma unroll 4
    for (int j = 0; j < cnt; j++) {
        const float aj = sh_a[j];
        const int   kj = sh_k[j];
        const float4 b = reinterpret_cast<const float4*>(&g_bT[kj][0])[tid];
        acc.x = fmaxf(acc.x, aj + b.x);
        acc.y = fmaxf(acc.y, aj + b.y);
        acc.z = fmaxf(acc.z, aj + b.z);
        acc.w = fmaxf(acc.w, aj + b.w);
    }
    reinterpret_cast<float4*>(out + n * M_)[tid] = acc;
}

// ---------------------------------------------------------------------------
extern "C" void kernel_launch(void* const* d_in, const int* in_sizes, int n_in,
                              void* d_out, int out_size) {
    const float* x = (const float*)d_in[0];   // [N, K] fp32
    const float* w = (const float*)d_in[1];   // [M, K] fp32
    float* out     = (float*)d_out;           // [N, M] fp32

    (void)in_sizes; (void)n_in; (void)out_size;

    absT_kernel<<<dim3(M_ / 32, K_ / 32), dim3(32, 8)>>>(w);
    tropical_rows_kernel<<<N_, 256>>>(x, out);
}